// round 6
// baseline (speedup 1.0000x reference)
#include <cuda_runtime.h>
#include <cuda_bf16.h>
#include <stdint.h>

// ---------------- problem constants ----------------
#define NFREQ  33
#define FC     66
#define FCP    80
#define BATCH  8
#define CIN    64
#define COUT   64
#define TLEN   16384
#define NFRAME 513
#define NFS    576           // padded frames per batch
#define MS     (BATCH*NFS)   // 4608 = 18*256

// ---------------- global scratch ----------------
__device__ __nv_bfloat16 g_Uh[(size_t)FC * CIN  * MS];
__device__ __nv_bfloat16 g_Ul[(size_t)FC * CIN  * MS];
__device__ __nv_bfloat16 g_Yh[(size_t)FC * COUT * MS];
__device__ __nv_bfloat16 g_Yl[(size_t)FC * COUT * MS];
__device__ __nv_bfloat16 g_Wh[(size_t)NFREQ * COUT * CIN];
__device__ __nv_bfloat16 g_Wl[(size_t)NFREQ * COUT * CIN];
__device__ __nv_bfloat16 g_Bth[FCP * 72], g_Btl[FCP * 72];   // [fc][t], pitch 144B
__device__ __nv_bfloat16 g_IDh[64 * 88],  g_IDl[64 * 88];    // [t'][fc], pitch 176B

__device__ __forceinline__ void mma_bf16(float* d, const uint32_t* a, const uint32_t* b) {
    asm volatile(
        "mma.sync.aligned.m16n8k16.row.col.f32.bf16.bf16.f32 "
        "{%0,%1,%2,%3}, {%4,%5,%6,%7}, {%8,%9}, {%0,%1,%2,%3};"
        : "+f"(d[0]), "+f"(d[1]), "+f"(d[2]), "+f"(d[3])
        : "r"(a[0]), "r"(a[1]), "r"(a[2]), "r"(a[3]), "r"(b[0]), "r"(b[1]));
}
__device__ __forceinline__ void ldsm4(uint32_t* r, uint32_t a) {
    asm volatile("ldmatrix.sync.aligned.m8n8.x4.shared.b16 {%0,%1,%2,%3}, [%4];"
        : "=r"(r[0]), "=r"(r[1]), "=r"(r[2]), "=r"(r[3]) : "r"(a));
}
__device__ __forceinline__ void ldsm4t(uint32_t* r, uint32_t a) {
    asm volatile("ldmatrix.sync.aligned.m8n8.x4.trans.shared.b16 {%0,%1,%2,%3}, [%4];"
        : "=r"(r[0]), "=r"(r[1]), "=r"(r[2]), "=r"(r[3]) : "r"(a));
}
__device__ __forceinline__ void ldsm2(uint32_t* r, uint32_t a) {
    asm volatile("ldmatrix.sync.aligned.m8n8.x2.shared.b16 {%0,%1}, [%2];"
        : "=r"(r[0]), "=r"(r[1]) : "r"(a));
}
__device__ __forceinline__ void split2(float v, uint16_t& h, uint16_t& l) {
    __nv_bfloat16 hb = __float2bfloat16(v);
    __nv_bfloat16 lb = __float2bfloat16(v - __bfloat162float(hb));
    h = *(uint16_t*)&hb; l = *(uint16_t*)&lb;
}

// =====================================================================
// table precompute
// =====================================================================
__global__ __launch_bounds__(256) void k_prep() {
    int tid0 = blockIdx.x * 256 + threadIdx.x;
    for (int idx = tid0; idx < FCP * 72; idx += 32 * 256) {
        int fc = idx / 72, t = idx - fc * 72;
        float v = 0.f;
        if (fc < FC && t < 64) {
            int f = fc >> 1;
            float s, c;
            sincospif((float)(f * t) / 32.0f, &s, &c);
            v = (fc & 1) ? -s : c;
            v *= 0.5f - 0.5f * cospif((float)t / 32.0f);
        }
        uint16_t h, l; split2(v, h, l);
        ((uint16_t*)g_Bth)[idx] = h; ((uint16_t*)g_Btl)[idx] = l;
    }
    for (int idx = tid0; idx < 64 * 88; idx += 32 * 256) {
        int t = idx / 88, fc = idx - t * 88;
        float v = 0.f;
        if (fc < FC) {
            int f = fc >> 1;
            float s, c;
            sincospif((float)(f * t) / 32.0f, &s, &c);
            float af = (f == 0 || f == 32) ? 1.0f : 2.0f;
            if (fc & 1) v = (f == 0 || f == 32) ? 0.f : -s * af;
            else        v = c * af;
            v *= (0.5f - 0.5f * cospif((float)t / 32.0f)) * (1.0f / 64.0f);
        }
        uint16_t h, l; split2(v, h, l);
        ((uint16_t*)g_IDh)[idx] = h; ((uint16_t*)g_IDl)[idx] = l;
    }
}

__global__ __launch_bounds__(256) void k_wprep(const float* __restrict__ weight) {
    int gid = blockIdx.x * 256 + threadIdx.x;
    if (gid >= NFREQ * COUT * CIN) return;
    int f = gid / (COUT * CIN);
    int rem = gid - f * (COUT * CIN);
    int o = rem >> 6, i = rem & 63;
    float w = weight[((size_t)o * CIN + i) * NFREQ + f];
    uint16_t h, l; split2(w, h, l);
    size_t dst = ((size_t)f * COUT + o) * CIN + i;
    ((uint16_t*)g_Wh)[dst] = h; ((uint16_t*)g_Wl)[dst] = l;
}

// =====================================================================
// Stage 1: STFT.  D[m=c(128)][n=fc(80)], K=t(64).
// A: frames [c][t] pitch 144 (non-trans ldmatrix); B: [fc][t] pitch 144.
// smem: AH@0(18432) AL@18432 BH@36864(11520) BL@48384; tot 59904
// Dt alias A: pitch 264
// =====================================================================
#define STFT_SMEM 59904
__global__ __launch_bounds__(256, 2) void k_stft(const float* __restrict__ x) {
    extern __shared__ __align__(16) char SM[];
    const uint32_t smb = (uint32_t)__cvta_generic_to_shared(SM);
    const int tid = threadIdx.x, w = tid >> 5, lane = tid & 31;
    const int g = lane >> 2, tig = lane & 3;
    const int mat = lane >> 3, row = lane & 7, matb = mat & 1;
    const int nch = blockIdx.x, i0 = blockIdx.y * 2, b = blockIdx.z;

    // stage frames [c][t]
    const float* xr = x + ((size_t)(b * CIN + i0)) * TLEN;
    for (int idx = tid; idx < 4160; idx += 256) {
        int il = idx >= 2080;
        int s = idx - il * 2080;
        int src = nch * 2048 + s - 32;
        src = src < 0 ? -src : src;
        src = src >= TLEN ? 2 * TLEN - 2 - src : src;
        float v = xr[(size_t)il * TLEN + src];
        uint16_t h, l; split2(v, h, l);
        int dn = s >> 5, t = s & 31;
        if (dn < 64) {
            int c = il * 64 + dn;
            *(uint16_t*)(SM + c * 144 + t * 2) = h;
            *(uint16_t*)(SM + 18432 + c * 144 + t * 2) = l;
        }
        if (dn >= 1) {
            int c = il * 64 + dn - 1;
            *(uint16_t*)(SM + c * 144 + (t + 32) * 2) = h;
            *(uint16_t*)(SM + 18432 + c * 144 + (t + 32) * 2) = l;
        }
    }
    // stage B tables (flat copy, pitch already 144)
    {
        const uint32_t* bh = (const uint32_t*)g_Bth;
        const uint32_t* bl = (const uint32_t*)g_Btl;
        for (int idx = tid; idx < 2880; idx += 256) {
            *(uint32_t*)(SM + 36864 + idx * 4) = bh[idx];
            *(uint32_t*)(SM + 48384 + idx * 4) = bl[idx];
        }
    }
    __syncthreads();

    const int mb = (w & 3) * 32, nb = (w >> 2) * 40;
    // A (non-trans) base: row m, col k
    const uint32_t aB = smb + (uint32_t)((mb + (mat & 1) * 8 + row) * 144 + (mat >> 1) * 16);
    const uint32_t bB = smb + 36864u + (uint32_t)((nb + row) * 144 + matb * 16);

    float d[2][5][4];
#pragma unroll
    for (int r = 0; r < 2; r++)
#pragma unroll
        for (int nt = 0; nt < 5; nt++)
#pragma unroll
            for (int q = 0; q < 4; q++) d[r][nt][q] = 0.f;

#pragma unroll
    for (int kc = 0; kc < 4; kc++) {
        uint32_t bh[5][2], bl[5][2];
#pragma unroll
        for (int nt = 0; nt < 5; nt++) {
            ldsm2(bh[nt], bB + nt * 1152 + kc * 32);
            ldsm2(bl[nt], bB + 11520 + nt * 1152 + kc * 32);
        }
#pragma unroll
        for (int r = 0; r < 2; r++) {
            uint32_t ah[4], al[4];
            ldsm4(ah, aB + r * 2304 + kc * 32);
            ldsm4(al, aB + 18432 + r * 2304 + kc * 32);
#pragma unroll
            for (int nt = 0; nt < 5; nt++) {
                mma_bf16(d[r][nt], ah, bh[nt]);
                mma_bf16(d[r][nt], al, bh[nt]);
                mma_bf16(d[r][nt], ah, bl[nt]);
            }
        }
    }
    __syncthreads();   // A dead -> Dt

    // Dt[fc][c] staging (pitch 264)
#pragma unroll
    for (int r = 0; r < 2; r++)
#pragma unroll
        for (int nt = 0; nt < 5; nt++) {
            int m = mb + r * 16 + g;
            int n = nb + nt * 8 + tig * 2;
            uint16_t h, l;
            if (n < FC) {
                split2(d[r][nt][0], h, l);
                *(uint16_t*)(SM + n * 264 + m * 2) = h;
                *(uint16_t*)(SM + 18432 + n * 264 + m * 2) = l;
                split2(d[r][nt][2], h, l);
                *(uint16_t*)(SM + n * 264 + (m + 8) * 2) = h;
                *(uint16_t*)(SM + 18432 + n * 264 + (m + 8) * 2) = l;
            }
            if (n + 1 < FC) {
                split2(d[r][nt][1], h, l);
                *(uint16_t*)(SM + (n + 1) * 264 + m * 2) = h;
                *(uint16_t*)(SM + 18432 + (n + 1) * 264 + m * 2) = l;
                split2(d[r][nt][3], h, l);
                *(uint16_t*)(SM + (n + 1) * 264 + (m + 8) * 2) = h;
                *(uint16_t*)(SM + 18432 + (n + 1) * 264 + (m + 8) * 2) = l;
            }
        }
    __syncthreads();

    uint32_t* uh = (uint32_t*)g_Uh;
    uint32_t* ul = (uint32_t*)g_Ul;
    const size_t cb = (size_t)b * NFS + nch * 64;
    for (int idx = tid; idx < 4224; idx += 256) {
        int rw = idx >> 5, wq = idx & 31;
        int fc = rw >> 1, il = rw & 1;
        uint32_t vh = *(uint32_t*)(SM + fc * 264 + il * 128 + wq * 4);
        uint32_t vl = *(uint32_t*)(SM + 18432 + fc * 264 + il * 128 + wq * 4);
        size_t di = ((((size_t)fc * CIN + i0 + il) * MS) + cb) >> 1;
        uh[di + wq] = vh;
        ul[di + wq] = vl;
    }
}

// =====================================================================
// Stage 2: mix.  D[m=c(256)][n=o(64)], K=i(64), per fc.
// A: Us[i][c] pitch 528 (ldmatrix.trans); B: W[o][i] pitch 144.
// smem: AH@0(33792) AL@33792 BH@67584(9216) BL@76800; tot 86016
// Dt alias A: [o][m] pitch 528
// =====================================================================
#define MIX_SMEM 86016
__global__ __launch_bounds__(256, 2) void k_mix() {
    extern __shared__ __align__(16) char SM[];
    const uint32_t smb = (uint32_t)__cvta_generic_to_shared(SM);
    const int tid = threadIdx.x, w = tid >> 5, lane = tid & 31;
    const int g = lane >> 2, tig = lane & 3;
    const int mat = lane >> 3, row = lane & 7, matb = mat & 1;
    const int fc = blockIdx.y, f = fc >> 1;
    const size_t c0 = (size_t)blockIdx.x * 256;

    // stage A (natural rows, coalesced)
    const uint32_t* uh = (const uint32_t*)g_Uh;
    const uint32_t* ul = (const uint32_t*)g_Ul;
    for (int idx = tid; idx < 8192; idx += 256) {
        int i = idx >> 7, q = idx & 127;
        size_t si = ((((size_t)fc * CIN + i) * MS) + c0) / 2 + q;
        *(uint32_t*)(SM + i * 528 + q * 4) = uh[si];
        *(uint32_t*)(SM + 33792 + i * 528 + q * 4) = ul[si];
    }
    // stage B
    {
        const uint32_t* wh = (const uint32_t*)g_Wh;
        const uint32_t* wl = (const uint32_t*)g_Wl;
        for (int idx = tid; idx < 2048; idx += 256) {
            int o = idx >> 5, wq = idx & 31;
            size_t si = ((size_t)f * COUT + o) * 32 + wq;
            *(uint32_t*)(SM + 67584 + o * 144 + wq * 4) = wh[si];
            *(uint32_t*)(SM + 76800 + o * 144 + wq * 4) = wl[si];
        }
    }
    __syncthreads();

    const int mb = (w & 3) * 64, nb = (w >> 2) * 32;
    const int krp = (mat >> 1) * 8 + row;
    const uint32_t aB = smb + (uint32_t)(krp * 528);
    const uint32_t bB = smb + 67584u + (uint32_t)((nb + row) * 144 + matb * 16);
    int mcol[4];
#pragma unroll
    for (int mt = 0; mt < 4; mt++) mcol[mt] = (mb + mt * 16 + (mat & 1) * 8) * 2;

    float d[4][4][4];
#pragma unroll
    for (int mt = 0; mt < 4; mt++)
#pragma unroll
        for (int nt = 0; nt < 4; nt++)
#pragma unroll
            for (int q = 0; q < 4; q++) d[mt][nt][q] = 0.f;

#pragma unroll
    for (int kc = 0; kc < 4; kc++) {
        uint32_t bh[4][2], bl[4][2];
#pragma unroll
        for (int nt = 0; nt < 4; nt++) {
            ldsm2(bh[nt], bB + nt * 1152 + kc * 32);
            ldsm2(bl[nt], bB + 9216 + nt * 1152 + kc * 32);
        }
#pragma unroll
        for (int mt = 0; mt < 4; mt++) {
            uint32_t ah[4], al[4];
            ldsm4t(ah, aB + kc * 8448 + mcol[mt]);
            ldsm4t(al, aB + 33792 + kc * 8448 + mcol[mt]);
#pragma unroll
            for (int nt = 0; nt < 4; nt++) {
                mma_bf16(d[mt][nt], ah, bh[nt]);
                mma_bf16(d[mt][nt], al, bh[nt]);
                mma_bf16(d[mt][nt], ah, bl[nt]);
            }
        }
    }
    __syncthreads();   // A dead -> Dt

#pragma unroll
    for (int mt = 0; mt < 4; mt++)
#pragma unroll
        for (int nt = 0; nt < 4; nt++) {
            int m = mb + mt * 16 + g;
            int oo = nb + nt * 8 + tig * 2;
            uint16_t h, l;
            split2(d[mt][nt][0], h, l);
            *(uint16_t*)(SM + oo * 528 + m * 2) = h;
            *(uint16_t*)(SM + 33792 + oo * 528 + m * 2) = l;
            split2(d[mt][nt][1], h, l);
            *(uint16_t*)(SM + (oo + 1) * 528 + m * 2) = h;
            *(uint16_t*)(SM + 33792 + (oo + 1) * 528 + m * 2) = l;
            split2(d[mt][nt][2], h, l);
            *(uint16_t*)(SM + oo * 528 + (m + 8) * 2) = h;
            *(uint16_t*)(SM + 33792 + oo * 528 + (m + 8) * 2) = l;
            split2(d[mt][nt][3], h, l);
            *(uint16_t*)(SM + (oo + 1) * 528 + (m + 8) * 2) = h;
            *(uint16_t*)(SM + 33792 + (oo + 1) * 528 + (m + 8) * 2) = l;
        }
    __syncthreads();

    uint32_t* yh = (uint32_t*)g_Yh;
    uint32_t* yl = (uint32_t*)g_Yl;
    for (int idx = tid; idx < 8192; idx += 256) {
        int o = idx >> 7, q = idx & 127;
        size_t di = ((((size_t)fc * COUT + o) * MS) + c0) / 2 + q;
        yh[di] = *(uint32_t*)(SM + o * 528 + q * 4);
        yl[di] = *(uint32_t*)(SM + 33792 + o * 528 + q * 4);
    }
}

// =====================================================================
// Stage 3+4: ISTFT frames + OLA.  D[m=c(256)][n=t'(64)], K=fc(80).
// A: Ys[fc][c] pitch 528 (trans); B: ID[t'][fc] pitch 176.
// smem: YsH@0(42240) YsL@42240 IDH@84480(11264) IDL@95744; tot 107008
// F (fp32, 257x68) aliases Ys.
// =====================================================================
#define FRAMES_SMEM 107008
__global__ __launch_bounds__(256, 2) void k_frames_ola(float* __restrict__ out) {
    extern __shared__ __align__(16) char SM[];
    __shared__ float yc[FC];
    __shared__ float inv[32];
    const uint32_t smb = (uint32_t)__cvta_generic_to_shared(SM);
    const int tid = threadIdx.x, w = tid >> 5, lane = tid & 31;
    const int g = lane >> 2, tig = lane & 3;
    const int mat = lane >> 3, row = lane & 7, matb = mat & 1;
    const int o = blockIdx.y;
    const size_t c0 = (size_t)blockIdx.x * 256;

    // stage Ys (natural rows) + zero pad fc 66..79
    const uint32_t* yh = (const uint32_t*)g_Yh;
    const uint32_t* yl = (const uint32_t*)g_Yl;
    for (int idx = tid; idx < 10240; idx += 256) {
        int fc = idx >> 7, q = idx & 127;
        uint32_t vh = 0, vl = 0;
        if (fc < FC) {
            size_t si = ((((size_t)fc * COUT + o) * MS) + c0) / 2 + q;
            vh = yh[si]; vl = yl[si];
        }
        *(uint32_t*)(SM + fc * 528 + q * 4) = vh;
        *(uint32_t*)(SM + 42240 + fc * 528 + q * 4) = vl;
    }
    // stage ID (flat copy, pitch 176)
    {
        const uint32_t* ih = (const uint32_t*)g_IDh;
        const uint32_t* il = (const uint32_t*)g_IDl;
        for (int idx = tid; idx < 2816; idx += 256) {
            *(uint32_t*)(SM + 84480 + idx * 4) = ih[idx];
            *(uint32_t*)(SM + 95744 + idx * 4) = il[idx];
        }
    }
    if (tid < FC) {
        float v = 0.f;
        if (blockIdx.x > 0) {
            size_t ei = ((size_t)tid * COUT + o) * MS + c0 - 1;
            v = __bfloat162float(g_Yh[ei]) + __bfloat162float(g_Yl[ei]);
        }
        yc[tid] = v;
    }
    if (tid < 32) {
        float c = cospif((float)tid / 32.0f);
        float w1 = 0.5f - 0.5f * c, w2 = 0.5f + 0.5f * c;
        inv[tid] = 1.0f / (w1 * w1 + w2 * w2);
    }
    __syncthreads();

    const int mb = (w & 3) * 64, nb = (w >> 2) * 32;
    const int krp = (mat >> 1) * 8 + row;
    const uint32_t aB = smb + (uint32_t)(krp * 528);
    const uint32_t bB = smb + 84480u + (uint32_t)((nb + row) * 176 + matb * 16);
    int mcol[4];
#pragma unroll
    for (int mt = 0; mt < 4; mt++) mcol[mt] = (mb + mt * 16 + (mat & 1) * 8) * 2;

    float d[4][4][4];
#pragma unroll
    for (int mt = 0; mt < 4; mt++)
#pragma unroll
        for (int nt = 0; nt < 4; nt++)
#pragma unroll
            for (int q = 0; q < 4; q++) d[mt][nt][q] = 0.f;

#pragma unroll
    for (int kc = 0; kc < 5; kc++) {
        uint32_t bh[4][2], bl[4][2];
#pragma unroll
        for (int nt = 0; nt < 4; nt++) {
            ldsm2(bh[nt], bB + nt * 1408 + kc * 32);
            ldsm2(bl[nt], bB + 11264 + nt * 1408 + kc * 32);
        }
#pragma unroll
        for (int mt = 0; mt < 4; mt++) {
            uint32_t ah[4], al[4];
            ldsm4t(ah, aB + kc * 8448 + mcol[mt]);
            ldsm4t(al, aB + 42240 + kc * 8448 + mcol[mt]);
#pragma unroll
            for (int nt = 0; nt < 4; nt++) {
                mma_bf16(d[mt][nt], ah, bh[nt]);
                mma_bf16(d[mt][nt], al, bh[nt]);
                mma_bf16(d[mt][nt], ah, bl[nt]);
            }
        }
    }

    // boundary frame (c0-1): taps 32..63
    float fm = 0.f;
    if (tid < 32) {
        int t = 32 + tid;
#pragma unroll 11
        for (int q = 0; q < FC; q++) {
            float idv = __bfloat162float(*(__nv_bfloat16*)(SM + 84480 + t * 176 + q * 2))
                      + __bfloat162float(*(__nv_bfloat16*)(SM + 95744 + t * 176 + q * 2));
            fm += idv * yc[q];
        }
    }
    __syncthreads();   // Ys dead -> F

    float* F = (float*)SM;   // F[i][t'] rows of 68; F[0] = frame c0-1
#pragma unroll
    for (int mt = 0; mt < 4; mt++)
#pragma unroll
        for (int nt = 0; nt < 4; nt++) {
            int m = mb + mt * 16 + g;
            int t = nb + nt * 8 + tig * 2;
            F[(1 + m) * 68 + t]     = d[mt][nt][0];
            F[(1 + m) * 68 + t + 1] = d[mt][nt][1];
            F[(9 + m) * 68 + t]     = d[mt][nt][2];
            F[(9 + m) * 68 + t + 1] = d[mt][nt][3];
        }
    if (tid < 32) F[32 + tid] = fm;
    __syncthreads();

    for (int sidx = tid; sidx < 8192; sidx += 256) {
        int i = sidx >> 5, r = sidx & 31;
        size_t m = c0 + i;
        int b = (int)(m / NFS);
        int n = (int)(m - (size_t)b * NFS);
        if (n < 1 || n >= NFRAME) continue;
        float v = (F[(i + 1) * 68 + r] + F[i * 68 + r + 32]) * inv[r];
        out[(((size_t)(b * COUT + o)) << 14) + (size_t)(n - 1) * 32 + r] = v;
    }
}

// =====================================================================
extern "C" void kernel_launch(void* const* d_in, const int* in_sizes, int n_in,
                              void* d_out, int out_size) {
    const float* x      = (const float*)d_in[0];
    const float* weight = (const float*)d_in[1];
    float* out          = (float*)d_out;
    (void)in_sizes; (void)n_in; (void)out_size;

    static int init = 0;
    if (!init) {
        cudaFuncSetAttribute(k_stft, cudaFuncAttributeMaxDynamicSharedMemorySize, STFT_SMEM);
        cudaFuncSetAttribute(k_mix, cudaFuncAttributeMaxDynamicSharedMemorySize, MIX_SMEM);
        cudaFuncSetAttribute(k_frames_ola, cudaFuncAttributeMaxDynamicSharedMemorySize, FRAMES_SMEM);
        init = 1;
    }

    k_wprep<<<(NFREQ * COUT * CIN + 255) / 256, 256>>>(weight);
    k_prep <<<32, 256>>>();
    k_stft <<<dim3(9, 32, 8), 256, STFT_SMEM>>>(x);
    k_mix  <<<dim3(MS / 256, FC), 256, MIX_SMEM>>>();
    k_frames_ola<<<dim3(MS / 256, COUT), 256, FRAMES_SMEM>>>(out);
}